// round 8
// baseline (speedup 1.0000x reference)
#include <cuda_runtime.h>

// GlobalContextAttention — j-pipelined fusion: overlap DRAM pass with L2 pass.
// x (J, F, C=128) fp32, batch_index (F,) int32 SORTED, weight (C,C) fp32 -> out (J, B, C).
//
// R7 lesson: with x read exactly once, pass1 (DRAM) and pass2 (L2) execute
// serially per CTA -> DRAM idles during pass2 windows (47% busy). Fix: each CTA
// owns (b, block of j's) and runs a fused steady-state loop that streams
// pass1(j) from DRAM while computing pass2(j-1) from L2 in the same body.
// Grid = B x 3 = 384 CTAs (single wave), live L2 set ~115MB < 126MB.

static constexpr int C_DIM   = 128;
static constexpr int THREADS = 384;
static constexpr int WARPS   = 12;
static constexpr int G_SPLIT = 3;
static constexpr int MAX_SEG = 4096;

__device__ int g_seg[MAX_SEG + 1];

__global__ void seg_bounds_kernel(const int* __restrict__ idx, int Fn, int Bn)
{
    const int t = blockIdx.x * blockDim.x + threadIdx.x;
    if (t > Bn) return;
    int lo = 0, hi = Fn;
    while (lo < hi) {
        int m = (lo + hi) >> 1;
        if (idx[m] < t) lo = m + 1; else hi = m;
    }
    g_seg[t] = lo;
}

__device__ __forceinline__ float warp_gate(float d) {
#pragma unroll
    for (int s = 16; s > 0; s >>= 1)
        d += __shfl_xor_sync(0xffffffffu, d, s);
    return 1.f / (1.f + __expf(-d));
}

__global__ __launch_bounds__(THREADS, 3)
void gca_fused_kernel(const float* __restrict__ x,
                      const float* __restrict__ W,
                      float*       __restrict__ out,
                      int Jn, int Fn, int Bn)
{
    __shared__ float s_p1[WARPS * C_DIM];   // pass1 partials (also gemv partials)
    __shared__ float s_p2[WARPS * C_DIM];   // pass2 partials
    __shared__ float s_vec[C_DIM];          // mean, then gc

    const int tid  = threadIdx.x;
    const int warp = tid >> 5;
    const int lane = tid & 31;
    const int b    = blockIdx.x;
    const int g    = blockIdx.y;

    const int jb = (g * Jn) / G_SPLIT;
    const int je = ((g + 1) * Jn) / G_SPLIT;
    if (jb >= je) return;

    const int start = g_seg[b];
    const int end   = g_seg[b + 1];
    const int cnt   = end - start;
    const float inv_cnt = 1.0f / (float)(cnt > 0 ? cnt : 1);
    const int ch = lane * 4;

    // ================= pass1 for j = jb (unfused, unroll 6) =================
    {
        const float* xj = x + (size_t)jb * Fn * C_DIM;
        float4 acc = make_float4(0.f, 0.f, 0.f, 0.f);
        int f = start + warp;
        for (; f + 5 * WARPS < end; f += 6 * WARPS) {
#pragma unroll
            for (int u = 0; u < 6; u++) {
                const float4 a = *(const float4*)(xj + (size_t)(f + u * WARPS) * C_DIM + ch);
                acc.x += a.x; acc.y += a.y; acc.z += a.z; acc.w += a.w;
            }
        }
        for (; f < end; f += WARPS) {
            const float4 a = *(const float4*)(xj + (size_t)f * C_DIM + ch);
            acc.x += a.x; acc.y += a.y; acc.z += a.z; acc.w += a.w;
        }
        *(float4*)&s_p1[warp * C_DIM + ch] = acc;
    }
    __syncthreads();
    if (tid < C_DIM) {
        float s = 0.f;
#pragma unroll
        for (int w = 0; w < WARPS; w++) s += s_p1[w * C_DIM + tid];
        s_vec[tid] = s * inv_cnt;           // mean[jb,b,:]
    }
    __syncthreads();
    // gemv gc = tanh(mean @ W): 256 threads, k split in two halves of 64
    if (tid < 256) {
        const int t_out = tid & (C_DIM - 1);
        const int half  = tid >> 7;
        const float* wp = W + (size_t)(half * 64) * C_DIM + t_out;
        float p = 0.f;
#pragma unroll 8
        for (int k = 0; k < 64; k++)
            p += s_vec[half * 64 + k] * wp[(size_t)k * C_DIM];
        s_p1[half * C_DIM + t_out] = p;
    }
    __syncthreads();
    if (tid < C_DIM)
        s_vec[tid] = tanhf(s_p1[tid] + s_p1[C_DIM + tid]);
    __syncthreads();

    // ================= steady state: pass1(j) fused with pass2(j-1) ==========
    for (int j = jb + 1; j < je; j++) {
        const float* xc = x + (size_t)j       * Fn * C_DIM;  // current (DRAM stream)
        const float* xp = x + (size_t)(j - 1) * Fn * C_DIM;  // previous (L2 re-read)
        const float4 gc4 = *(const float4*)&s_vec[ch];

        float4 a1 = make_float4(0.f, 0.f, 0.f, 0.f);   // pass1 acc
        float4 a2 = make_float4(0.f, 0.f, 0.f, 0.f);   // pass2 acc
        int f = start + warp;
        for (; f + WARPS < end; f += 2 * WARPS) {
            // issue all 4 loads up front (2 DRAM + 2 L2 in flight)
            const float4 n0 = *(const float4*)(xc + (size_t)(f        ) * C_DIM + ch);
            const float4 n1 = *(const float4*)(xc + (size_t)(f + WARPS) * C_DIM + ch);
            const float4 o0 = *(const float4*)(xp + (size_t)(f        ) * C_DIM + ch);
            const float4 o1 = *(const float4*)(xp + (size_t)(f + WARPS) * C_DIM + ch);
            a1.x += n0.x + n1.x; a1.y += n0.y + n1.y;
            a1.z += n0.z + n1.z; a1.w += n0.w + n1.w;
            float d0 = o0.x*gc4.x + o0.y*gc4.y + o0.z*gc4.z + o0.w*gc4.w;
            float d1 = o1.x*gc4.x + o1.y*gc4.y + o1.z*gc4.z + o1.w*gc4.w;
#pragma unroll
            for (int s = 16; s > 0; s >>= 1) {
                d0 += __shfl_xor_sync(0xffffffffu, d0, s);
                d1 += __shfl_xor_sync(0xffffffffu, d1, s);
            }
            const float g0 = 1.f / (1.f + __expf(-d0));
            const float g1 = 1.f / (1.f + __expf(-d1));
            a2.x += g0*o0.x + g1*o1.x; a2.y += g0*o0.y + g1*o1.y;
            a2.z += g0*o0.z + g1*o1.z; a2.w += g0*o0.w + g1*o1.w;
        }
        for (; f < end; f += WARPS) {
            const float4 n0 = *(const float4*)(xc + (size_t)f * C_DIM + ch);
            const float4 o0 = *(const float4*)(xp + (size_t)f * C_DIM + ch);
            a1.x += n0.x; a1.y += n0.y; a1.z += n0.z; a1.w += n0.w;
            const float g0 = warp_gate(o0.x*gc4.x + o0.y*gc4.y + o0.z*gc4.z + o0.w*gc4.w);
            a2.x += g0*o0.x; a2.y += g0*o0.y; a2.z += g0*o0.z; a2.w += g0*o0.w;
        }
        *(float4*)&s_p1[warp * C_DIM + ch] = a1;
        *(float4*)&s_p2[warp * C_DIM + ch] = a2;
        __syncthreads();
        if (tid < C_DIM) {
            float s2 = 0.f, s1 = 0.f;
#pragma unroll
            for (int w = 0; w < WARPS; w++) {
                s2 += s_p2[w * C_DIM + tid];
                s1 += s_p1[w * C_DIM + tid];
            }
            out[((size_t)(j - 1) * Bn + b) * C_DIM + tid] = s2 * inv_cnt;
            s_vec[tid] = s1 * inv_cnt;       // mean[j,b,:]
        }
        __syncthreads();
        if (tid < 256) {
            const int t_out = tid & (C_DIM - 1);
            const int half  = tid >> 7;
            const float* wp = W + (size_t)(half * 64) * C_DIM + t_out;
            float p = 0.f;
#pragma unroll 8
            for (int k = 0; k < 64; k++)
                p += s_vec[half * 64 + k] * wp[(size_t)k * C_DIM];
            s_p1[half * C_DIM + t_out] = p;
        }
        __syncthreads();
        if (tid < C_DIM)
            s_vec[tid] = tanhf(s_p1[tid] + s_p1[C_DIM + tid]);
        __syncthreads();
    }

    // ================= drain: pass2 for j = je-1 (unfused, unroll 4) =========
    {
        const float* xp = x + (size_t)(je - 1) * Fn * C_DIM;
        const float4 gc4 = *(const float4*)&s_vec[ch];
        float4 a2 = make_float4(0.f, 0.f, 0.f, 0.f);
        int f = start + warp;
        for (; f + 3 * WARPS < end; f += 4 * WARPS) {
            float4 o[4];
#pragma unroll
            for (int u = 0; u < 4; u++)
                o[u] = *(const float4*)(xp + (size_t)(f + u * WARPS) * C_DIM + ch);
            float d[4];
#pragma unroll
            for (int u = 0; u < 4; u++)
                d[u] = o[u].x*gc4.x + o[u].y*gc4.y + o[u].z*gc4.z + o[u].w*gc4.w;
#pragma unroll
            for (int s = 16; s > 0; s >>= 1) {
#pragma unroll
                for (int u = 0; u < 4; u++)
                    d[u] += __shfl_xor_sync(0xffffffffu, d[u], s);
            }
#pragma unroll
            for (int u = 0; u < 4; u++) {
                const float gg = 1.f / (1.f + __expf(-d[u]));
                a2.x += gg*o[u].x; a2.y += gg*o[u].y; a2.z += gg*o[u].z; a2.w += gg*o[u].w;
            }
        }
        for (; f < end; f += WARPS) {
            const float4 o0 = *(const float4*)(xp + (size_t)f * C_DIM + ch);
            const float gg = warp_gate(o0.x*gc4.x + o0.y*gc4.y + o0.z*gc4.z + o0.w*gc4.w);
            a2.x += gg*o0.x; a2.y += gg*o0.y; a2.z += gg*o0.z; a2.w += gg*o0.w;
        }
        *(float4*)&s_p2[warp * C_DIM + ch] = a2;
        __syncthreads();
        if (tid < C_DIM) {
            float s = 0.f;
#pragma unroll
            for (int w = 0; w < WARPS; w++) s += s_p2[w * C_DIM + tid];
            out[((size_t)(je - 1) * Bn + b) * C_DIM + tid] = s * inv_cnt;
        }
    }
}

extern "C" void kernel_launch(void* const* d_in, const int* in_sizes, int n_in,
                              void* d_out, int out_size)
{
    // Identify inputs by element count: x = largest; weight = C*C; idx = other multi-element.
    int xi = 0;
    for (int i = 1; i < n_in; i++)
        if (in_sizes[i] > in_sizes[xi]) xi = i;
    int wi = -1, ii = -1;
    for (int i = 0; i < n_in; i++) {
        if (i == xi) continue;
        if (in_sizes[i] == C_DIM * C_DIM && wi < 0) { wi = i; continue; }
        if (in_sizes[i] > 1 && ii < 0) ii = i;
    }
    if (wi < 0 || ii < 0) return;

    const float* x   = (const float*)d_in[xi];
    const int*   idx = (const int*)  d_in[ii];
    const float* W   = (const float*)d_in[wi];
    float*       out = (float*)d_out;

    const int Fn = in_sizes[ii];
    const int Jn = in_sizes[xi] / (Fn * C_DIM);
    int Bn = out_size / (Jn * C_DIM);
    if (Bn > MAX_SEG) Bn = MAX_SEG;

    seg_bounds_kernel<<<(Bn + 255) / 256 + 1, 256>>>(idx, Fn, Bn);
    dim3 grid(Bn, G_SPLIT);
    gca_fused_kernel<<<grid, THREADS>>>(x, W, out, Jn, Fn, Bn);
}